// round 5
// baseline (speedup 1.0000x reference)
#include <cuda_runtime.h>
#include <cuda_bf16.h>
#include <math_constants.h>
#include <cstdint>

#define NB 8
#define NQ 2048
#define NK 2048
#define ND 1024

// ---------------------------------------------------------------------------
// Scratch (device globals)
// Q' rows: [Qhi | Qlo]   pitch 2048
// K' rows: [Khi | Klo]   pitch 2048
// V^T' rows (d-major, recip-scaled): [Vhi | Vlo] pitch 4096
// E' rows (unnormalized exp): [Ehi | Elo] pitch 4096
// ---------------------------------------------------------------------------
__device__ __nv_bfloat16 gQp[(size_t)NB * NQ * 2048];
__device__ __nv_bfloat16 gKp[(size_t)NB * NK * 2048];
__device__ __nv_bfloat16 gVT[(size_t)NB * ND * 4096];
__device__ __nv_bfloat16 gEp[(size_t)NB * NQ * 4096];
__device__ float gS[(size_t)NB * NQ * NK];
__device__ unsigned gMax[NB * NK];
__device__ float gRecip[NB * NK];

// ---------------------------------------------------------------------------
__device__ __forceinline__ uint32_t smem_u32(const void* p) {
    uint32_t a;
    asm("{ .reg .u64 t; cvta.to.shared.u64 t, %1; cvt.u32.u64 %0, t; }"
        : "=r"(a) : "l"(p));
    return a;
}

#define CP_ASYNC16(dst, src) \
    asm volatile("cp.async.cg.shared.global [%0], [%1], 16;" :: "r"(dst), "l"(src))
#define CP_COMMIT() asm volatile("cp.async.commit_group;" ::: "memory")
#define CP_WAIT2()  asm volatile("cp.async.wait_group 2;" ::: "memory")

#define LDSM_X4(r0, r1, r2, r3, addr) \
    asm volatile("ldmatrix.sync.aligned.m8n8.x4.shared.b16 {%0,%1,%2,%3}, [%4];" \
                 : "=r"(r0), "=r"(r1), "=r"(r2), "=r"(r3) : "r"(addr))

#define MMA16816(d, a, b) \
    asm volatile("mma.sync.aligned.m16n8k16.row.col.f32.bf16.bf16.f32 " \
                 "{%0,%1,%2,%3}, {%4,%5,%6,%7}, {%8,%9}, {%0,%1,%2,%3};" \
                 : "+f"((d)[0]), "+f"((d)[1]), "+f"((d)[2]), "+f"((d)[3]) \
                 : "r"((a)[0]), "r"((a)[1]), "r"((a)[2]), "r"((a)[3]), \
                   "r"((b)[0]), "r"((b)[1]))

__device__ __forceinline__ unsigned fmax_flip(float f) {
    unsigned u = __float_as_uint(f);
    return (u & 0x80000000u) ? ~u : (u | 0x80000000u);
}
__device__ __forceinline__ float fmax_unflip(unsigned u) {
    return (u & 0x80000000u) ? __uint_as_float(u ^ 0x80000000u)
                             : __uint_as_float(~u);
}

// ---------------------------------------------------------------------------
// Prep: split Q and K into bf16 [hi|lo], pitch 2048. Also zeroes gMax.
// ---------------------------------------------------------------------------
__global__ __launch_bounds__(256) void split_qk(const float* __restrict__ Qm,
                                                const float* __restrict__ Km) {
    const int row = blockIdx.x;
    const int isK = blockIdx.y;
    if (!isK && row < 64) gMax[row * 256 + threadIdx.x] = 0u;

    const float* src = (isK ? Km : Qm) + (size_t)row * ND;
    __nv_bfloat16* dst = (isK ? gKp : gQp) + (size_t)row * 2048;

    const int c = threadIdx.x * 4;
    float4 v = *(const float4*)(src + c);
    float f[4] = {v.x, v.y, v.z, v.w};
    __nv_bfloat16 hi[4], lo[4];
#pragma unroll
    for (int i = 0; i < 4; i++) {
        hi[i] = __float2bfloat16_rn(f[i]);
        lo[i] = __float2bfloat16_rn(f[i] - __bfloat162float(hi[i]));
    }
    __nv_bfloat162* dh = (__nv_bfloat162*)(dst + c);
    dh[0] = __nv_bfloat162(hi[0], hi[1]);
    dh[1] = __nv_bfloat162(hi[2], hi[3]);
    __nv_bfloat162* dl = (__nv_bfloat162*)(dst + 1024 + c);
    dl[0] = __nv_bfloat162(lo[0], lo[1]);
    dl[1] = __nv_bfloat162(lo[2], lo[3]);
}

// ---------------------------------------------------------------------------
// Transpose V (k,d)->(d,k), scale rows by recip[k], split hi/lo (pitch 4096).
// ---------------------------------------------------------------------------
__global__ __launch_bounds__(256) void transpose_v(const float* __restrict__ Vm) {
    __shared__ float t[32][33];
    const int b = blockIdx.z;
    const int d0 = blockIdx.x * 32;
    const int k0 = blockIdx.y * 32;
    const int tx = threadIdx.x & 31;
    const int ty = threadIdx.x >> 5;

    const float* src = Vm + (size_t)b * NK * ND;
#pragma unroll
    for (int i = 0; i < 4; i++) {
        int kk = k0 + ty + i * 8;
        t[ty + i * 8][tx] = src[(size_t)kk * ND + d0 + tx] * gRecip[b * NK + kk];
    }
    __syncthreads();

    __nv_bfloat16* dst = gVT + (size_t)b * ND * 4096;
#pragma unroll
    for (int i = 0; i < 4; i++) {
        int dd = ty + i * 8;
        float x = t[tx][dd];
        __nv_bfloat16 hi = __float2bfloat16_rn(x);
        __nv_bfloat16 lo = __float2bfloat16_rn(x - __bfloat162float(hi));
        __nv_bfloat16* r = dst + (size_t)(d0 + dd) * 4096 + k0 + tx;
        r[0]    = hi;
        r[2048] = lo;
    }
}

// ---------------------------------------------------------------------------
// bf16 warp-MMA GEMM, 3-phase hi/lo emulation walk:
//   phase0: A hi, B hi   phase1: A hi, B lo   phase2: A lo, B hi
// Block tile 128(M) x 256(N), 8 warps (2M x 4N), warp tile 64x64, BK=32.
// 4-stage cp.async, ONE __syncthreads per chunk (distance-3 prefetch).
// ---------------------------------------------------------------------------
#define PITCH 80
#define A_BYTES (128 * PITCH)            // 10240
#define STAGE_BYTES (384 * PITCH)        // A(128) + B(256) rows = 30720

__global__ __launch_bounds__(256, 1) void tc_gemm(
    const __nv_bfloat16* __restrict__ A, const __nv_bfloat16* __restrict__ B,
    float* __restrict__ C, int lda, int ldb, int ldc, int pchunks,
    size_t sA, size_t sB, size_t sC, unsigned* maxArr) {
    extern __shared__ char dsmem[];

    const int tid = threadIdx.x;
    const int wid = tid >> 5;
    const int lane = tid & 31;
    const int warp_m = wid & 1;          // 2 M-slabs of 64
    const int warp_n = wid >> 1;         // 4 N-slabs of 64
    const int b = blockIdx.z;
    const int nchunk = 3 * pchunks;

    const __nv_bfloat16* Ag = A + b * sA + (size_t)blockIdx.y * 128 * lda;
    const __nv_bfloat16* Bg = B + b * sB + (size_t)blockIdx.x * 256 * ldb;
    float* Cg = C + b * sC + (size_t)blockIdx.y * 128 * ldc + (size_t)blockIdx.x * 256;

    const uint32_t sbase = smem_u32(dsmem);

    float acc[4][8][4];
#pragma unroll
    for (int mt = 0; mt < 4; mt++)
#pragma unroll
        for (int nt = 0; nt < 8; nt++)
#pragma unroll
            for (int i = 0; i < 4; i++) acc[mt][nt][i] = 0.f;

    // cp.async mapping: granule = 16B; A has 512 slots, B has 1024 slots.
    const int gr = tid & 3;              // granule in row (4 x 16B = 64B)
    const int r0 = tid >> 2;             // 0..63

    auto load_chunk = [&](int c, int stage) {
        int ac, bc;
        if (c < pchunks)          { ac = c;            bc = c; }
        else if (c < 2 * pchunks) { ac = c - pchunks;  bc = c; }
        else                      { ac = c - pchunks;  bc = c - 2 * pchunks; }
        uint32_t sa = sbase + stage * STAGE_BYTES;
        uint32_t sb = sa + A_BYTES;
        const __nv_bfloat16* As = Ag + ac * 32;
        const __nv_bfloat16* Bs = Bg + bc * 32;
#pragma unroll
        for (int p = 0; p < 2; p++) {
            int row = r0 + p * 64;
            uint32_t off = (uint32_t)row * PITCH + gr * 16u;
            CP_ASYNC16(sa + off, As + (size_t)row * lda + gr * 8);
        }
#pragma unroll
        for (int p = 0; p < 4; p++) {
            int row = r0 + p * 64;
            uint32_t off = (uint32_t)row * PITCH + gr * 16u;
            CP_ASYNC16(sb + off, Bs + (size_t)row * ldb + gr * 8);
        }
    };

    load_chunk(0, 0); CP_COMMIT();
    load_chunk(1, 1); CP_COMMIT();
    load_chunk(2, 2); CP_COMMIT();

    const int lrow = lane & 15;
    const int lcol = (lane >> 4) * 16;

    for (int c = 0; c < nchunk; ++c) {
        CP_WAIT2();
        __syncthreads();
        if (c + 3 < nchunk) { load_chunk(c + 3, (c + 3) & 3); }
        CP_COMMIT();

        const int s = c & 3;
        uint32_t sa = sbase + s * STAGE_BYTES;
        uint32_t sb = sa + A_BYTES;

#pragma unroll
        for (int ks = 0; ks < 2; ks++) {
            uint32_t afrag[4][4];
#pragma unroll
            for (int mt = 0; mt < 4; mt++) {
                uint32_t addr = sa + (uint32_t)(warp_m * 64 + mt * 16 + lrow) * PITCH
                              + ks * 32 + lcol;
                LDSM_X4(afrag[mt][0], afrag[mt][1], afrag[mt][2], afrag[mt][3], addr);
            }
            uint32_t bfrag[8][2];
#pragma unroll
            for (int nq = 0; nq < 4; nq++) {
                uint32_t t0, t1, t2, t3;
                uint32_t addr = sb + (uint32_t)(warp_n * 64 + nq * 16 + lrow) * PITCH
                              + ks * 32 + lcol;
                LDSM_X4(t0, t1, t2, t3, addr);
                bfrag[nq * 2 + 0][0] = t0; bfrag[nq * 2 + 0][1] = t2;
                bfrag[nq * 2 + 1][0] = t1; bfrag[nq * 2 + 1][1] = t3;
            }
#pragma unroll
            for (int mt = 0; mt < 4; mt++)
#pragma unroll
                for (int nt = 0; nt < 8; nt++)
                    MMA16816(acc[mt][nt], afrag[mt], bfrag[nt]);
        }
    }
    __syncthreads();

    // epilogue
    const int crow = lane >> 2;
    const int ccol = (lane & 3) * 2;
#pragma unroll
    for (int mt = 0; mt < 4; mt++) {
#pragma unroll
        for (int nt = 0; nt < 8; nt++) {
            float* p = Cg + (size_t)(warp_m * 64 + mt * 16 + crow) * ldc
                         + warp_n * 64 + nt * 8 + ccol;
            *(float2*)p = make_float2(acc[mt][nt][0], acc[mt][nt][1]);
            *(float2*)(p + 8 * ldc) = make_float2(acc[mt][nt][2], acc[mt][nt][3]);
        }
    }
    if (maxArr) {
        unsigned* mrow = maxArr + b * NK + blockIdx.x * 256 + warp_n * 64;
#pragma unroll
        for (int nt = 0; nt < 8; nt++) {
            float c0 = -CUDART_INF_F, c1 = -CUDART_INF_F;
#pragma unroll
            for (int mt = 0; mt < 4; mt++) {
                c0 = fmaxf(c0, fmaxf(acc[mt][nt][0], acc[mt][nt][2]));
                c1 = fmaxf(c1, fmaxf(acc[mt][nt][1], acc[mt][nt][3]));
            }
#pragma unroll
            for (int off = 4; off < 32; off <<= 1) {
                c0 = fmaxf(c0, __shfl_xor_sync(0xffffffffu, c0, off));
                c1 = fmaxf(c1, __shfl_xor_sync(0xffffffffu, c1, off));
            }
            if (lane < 4) {
                atomicMax(&mrow[nt * 8 + (lane & 3) * 2],     fmax_flip(c0));
                atomicMax(&mrow[nt * 8 + (lane & 3) * 2 + 1], fmax_flip(c1));
            }
        }
    }
}

// ---------------------------------------------------------------------------
// Single-pass column softmax using precomputed max.
// ---------------------------------------------------------------------------
__global__ __launch_bounds__(256) void col_softmax() {
    const int blk = blockIdx.x;
    const int b = blk / (NK / 32);
    const int kbase = (blk % (NK / 32)) * 32;
    const int tid = threadIdx.x;
    const int c = tid & 31;
    const int rg = tid >> 5;

    const float* S = gS + (size_t)b * NQ * NK + kbase;
    __nv_bfloat16* E = gEp + (size_t)b * NQ * 4096 + kbase;
    __shared__ float red[8][32];

    const float m = fmax_unflip(gMax[b * NK + kbase + c]);

    float sum = 0.f;
#pragma unroll 4
    for (int q = rg; q < NQ; q += 8) {
        float e = __expf(S[(size_t)q * NK + c] - m);
        __nv_bfloat16 hi = __float2bfloat16_rn(e);
        __nv_bfloat16 lo = __float2bfloat16_rn(e - __bfloat162float(hi));
        __nv_bfloat16* r = E + (size_t)q * 4096;
        r[c]        = hi;
        r[2048 + c] = lo;
        sum += e;
    }
    red[rg][c] = sum;
    __syncthreads();
    if (rg == 0) {
        float s = 0.f;
#pragma unroll
        for (int r = 0; r < 8; r++) s += red[r][c];
        gRecip[b * NK + kbase + c] = 1.0f / s;
    }
}

// ---------------------------------------------------------------------------
extern "C" void kernel_launch(void* const* d_in, const int* in_sizes, int n_in,
                              void* d_out, int out_size) {
    const float* Qm = (const float*)d_in[0];
    const float* Km = (const float*)d_in[1];
    const float* Vm = (const float*)d_in[2];
    float* Out = (float*)d_out;

    void *pQ, *pK, *pV, *pE, *pS, *pMax;
    cudaGetSymbolAddress(&pQ, gQp);
    cudaGetSymbolAddress(&pK, gKp);
    cudaGetSymbolAddress(&pV, gVT);
    cudaGetSymbolAddress(&pE, gEp);
    cudaGetSymbolAddress(&pS, gS);
    cudaGetSymbolAddress(&pMax, gMax);

    const int SMEM = 4 * STAGE_BYTES;   // 122880
    static bool attr_done = false;
    if (!attr_done) {
        cudaFuncSetAttribute(tc_gemm, cudaFuncAttributeMaxDynamicSharedMemorySize, SMEM);
        attr_done = true;
    }

    split_qk<<<dim3(NB * NQ, 2), 256>>>(Qm, Km);

    // S = Q' @ K'^T with fused column-max  (tiles: 256 K-cols x 128 Q-rows)
    tc_gemm<<<dim3(NK / 256, NQ / 128, NB), 256, SMEM>>>(
        (const __nv_bfloat16*)pQ, (const __nv_bfloat16*)pK, (float*)pS,
        2048, 2048, NK, 32,
        (size_t)NQ * 2048, (size_t)NK * 2048, (size_t)NQ * NK,
        (unsigned*)pMax);

    col_softmax<<<NB * (NK / 32), 256>>>();

    transpose_v<<<dim3(ND / 32, NK / 32, NB), 256>>>(Vm);

    // Out = E' @ VT'^T
    tc_gemm<<<dim3(ND / 256, NQ / 128, NB), 256, SMEM>>>(
        (const __nv_bfloat16*)pE, (const __nv_bfloat16*)pV, Out,
        4096, 4096, ND, 64,
        (size_t)NQ * 4096, (size_t)ND * 4096, (size_t)NQ * ND,
        (unsigned*)nullptr);
}

// round 6
// speedup vs baseline: 1.2660x; 1.2660x over previous
#include <cuda_runtime.h>
#include <cuda_bf16.h>
#include <math_constants.h>
#include <cstdint>

#define NB 8
#define NQ 2048
#define NK 2048
#define ND 1024

// ---------------------------------------------------------------------------
// Scratch (device globals)
// Q' rows: [Qhi | Qlo]   pitch 2048
// K' rows: [Khi | Klo]   pitch 2048
// V^T' rows (d-major, recip-scaled): [Vhi | Vlo] pitch 4096
// E' rows (unnormalized exp): [Ehi | Elo] pitch 4096
// ---------------------------------------------------------------------------
__device__ __nv_bfloat16 gQp[(size_t)NB * NQ * 2048];
__device__ __nv_bfloat16 gKp[(size_t)NB * NK * 2048];
__device__ __nv_bfloat16 gVT[(size_t)NB * ND * 4096];
__device__ __nv_bfloat16 gEp[(size_t)NB * NQ * 4096];
__device__ float gS[(size_t)NB * NQ * NK];
__device__ unsigned gMax[NB * NK];
__device__ float gRecip[NB * NK];

// ---------------------------------------------------------------------------
__device__ __forceinline__ uint32_t smem_u32(const void* p) {
    uint32_t a;
    asm("{ .reg .u64 t; cvta.to.shared.u64 t, %1; cvt.u32.u64 %0, t; }"
        : "=r"(a) : "l"(p));
    return a;
}

#define CP_ASYNC16(dst, src) \
    asm volatile("cp.async.cg.shared.global [%0], [%1], 16;" :: "r"(dst), "l"(src))
#define CP_COMMIT() asm volatile("cp.async.commit_group;" ::: "memory")
#define CP_WAIT1()  asm volatile("cp.async.wait_group 1;" ::: "memory")

#define LDSM_X4(r0, r1, r2, r3, addr) \
    asm volatile("ldmatrix.sync.aligned.m8n8.x4.shared.b16 {%0,%1,%2,%3}, [%4];" \
                 : "=r"(r0), "=r"(r1), "=r"(r2), "=r"(r3) : "r"(addr))

#define MMA16816(d, a, b) \
    asm volatile("mma.sync.aligned.m16n8k16.row.col.f32.bf16.bf16.f32 " \
                 "{%0,%1,%2,%3}, {%4,%5,%6,%7}, {%8,%9}, {%0,%1,%2,%3};" \
                 : "+f"((d)[0]), "+f"((d)[1]), "+f"((d)[2]), "+f"((d)[3]) \
                 : "r"((a)[0]), "r"((a)[1]), "r"((a)[2]), "r"((a)[3]), \
                   "r"((b)[0]), "r"((b)[1]))

__device__ __forceinline__ unsigned fmax_flip(float f) {
    unsigned u = __float_as_uint(f);
    return (u & 0x80000000u) ? ~u : (u | 0x80000000u);
}
__device__ __forceinline__ float fmax_unflip(unsigned u) {
    return (u & 0x80000000u) ? __uint_as_float(u ^ 0x80000000u)
                             : __uint_as_float(~u);
}

// ---------------------------------------------------------------------------
// Prep: split Q and K into bf16 [hi|lo], pitch 2048. Also zeroes gMax.
// ---------------------------------------------------------------------------
__global__ __launch_bounds__(256) void split_qk(const float* __restrict__ Qm,
                                                const float* __restrict__ Km) {
    const int row = blockIdx.x;
    const int isK = blockIdx.y;
    if (!isK && row < 64) gMax[row * 256 + threadIdx.x] = 0u;

    const float* src = (isK ? Km : Qm) + (size_t)row * ND;
    __nv_bfloat16* dst = (isK ? gKp : gQp) + (size_t)row * 2048;

    const int c = threadIdx.x * 4;
    float4 v = *(const float4*)(src + c);
    float f[4] = {v.x, v.y, v.z, v.w};
    __nv_bfloat16 hi[4], lo[4];
#pragma unroll
    for (int i = 0; i < 4; i++) {
        hi[i] = __float2bfloat16_rn(f[i]);
        lo[i] = __float2bfloat16_rn(f[i] - __bfloat162float(hi[i]));
    }
    __nv_bfloat162* dh = (__nv_bfloat162*)(dst + c);
    dh[0] = __nv_bfloat162(hi[0], hi[1]);
    dh[1] = __nv_bfloat162(hi[2], hi[3]);
    __nv_bfloat162* dl = (__nv_bfloat162*)(dst + 1024 + c);
    dl[0] = __nv_bfloat162(lo[0], lo[1]);
    dl[1] = __nv_bfloat162(lo[2], lo[3]);
}

// ---------------------------------------------------------------------------
// Transpose V (k,d)->(d,k), scale rows by recip[k], split hi/lo (pitch 4096).
// ---------------------------------------------------------------------------
__global__ __launch_bounds__(256) void transpose_v(const float* __restrict__ Vm) {
    __shared__ float t[32][33];
    const int b = blockIdx.z;
    const int d0 = blockIdx.x * 32;
    const int k0 = blockIdx.y * 32;
    const int tx = threadIdx.x & 31;
    const int ty = threadIdx.x >> 5;

    const float* src = Vm + (size_t)b * NK * ND;
#pragma unroll
    for (int i = 0; i < 4; i++) {
        int kk = k0 + ty + i * 8;
        t[ty + i * 8][tx] = src[(size_t)kk * ND + d0 + tx] * gRecip[b * NK + kk];
    }
    __syncthreads();

    __nv_bfloat16* dst = gVT + (size_t)b * ND * 4096;
#pragma unroll
    for (int i = 0; i < 4; i++) {
        int dd = ty + i * 8;
        float x = t[tx][dd];
        __nv_bfloat16 hi = __float2bfloat16_rn(x);
        __nv_bfloat16 lo = __float2bfloat16_rn(x - __bfloat162float(hi));
        __nv_bfloat16* r = dst + (size_t)(d0 + dd) * 4096 + k0 + tx;
        r[0]    = hi;
        r[2048] = lo;
    }
}

// ---------------------------------------------------------------------------
// bf16 warp-MMA GEMM, 3-phase hi/lo emulation walk:
//   phase0: A hi, B hi   phase1: A hi, B lo   phase2: A lo, B hi
// Block tile 128x128, 8 warps (4M x 2N), warp tile 32x64, BK=64.
// 3-stage cp.async, ONE __syncthreads per chunk (distance-2 prefetch).
// ---------------------------------------------------------------------------
#define PITCH 144                         // 128B data + 16 pad (conflict-free)
#define STAGE_BYTES (256 * PITCH)         // A(128 rows) + B(128 rows) = 36864

__global__ __launch_bounds__(256, 2) void tc_gemm(
    const __nv_bfloat16* __restrict__ A, const __nv_bfloat16* __restrict__ B,
    float* __restrict__ C, int lda, int ldb, int ldc, int pchunks,
    size_t sA, size_t sB, size_t sC, unsigned* maxArr) {
    extern __shared__ char dsmem[];

    const int tid = threadIdx.x;
    const int wid = tid >> 5;
    const int lane = tid & 31;
    const int warp_m = wid & 3;
    const int warp_n = wid >> 2;
    const int b = blockIdx.z;
    const int nchunk = 3 * pchunks;

    const __nv_bfloat16* Ag = A + b * sA + (size_t)blockIdx.y * 128 * lda;
    const __nv_bfloat16* Bg = B + b * sB + (size_t)blockIdx.x * 128 * ldb;
    float* Cg = C + b * sC + (size_t)blockIdx.y * 128 * ldc + (size_t)blockIdx.x * 128;

    const uint32_t sbase = smem_u32(dsmem);
    const int gr = tid & 7;               // 16B granule within 128B row
    const int r0 = tid >> 3;              // 0..31

    float acc[2][8][4];
#pragma unroll
    for (int mt = 0; mt < 2; mt++)
#pragma unroll
        for (int nt = 0; nt < 8; nt++)
#pragma unroll
            for (int i = 0; i < 4; i++) acc[mt][nt][i] = 0.f;

    auto load_chunk = [&](int c, int stage) {
        int ac, bc;
        if (c < pchunks)          { ac = c;            bc = c; }
        else if (c < 2 * pchunks) { ac = c - pchunks;  bc = c; }
        else                      { ac = c - pchunks;  bc = c - 2 * pchunks; }
        uint32_t sa = sbase + stage * STAGE_BYTES;
        uint32_t sb = sa + 128 * PITCH;
        const __nv_bfloat16* As = Ag + ac * 64;
        const __nv_bfloat16* Bs = Bg + bc * 64;
#pragma unroll
        for (int p = 0; p < 4; p++) {
            int row = r0 + p * 32;
            uint32_t off = (uint32_t)row * PITCH + gr * 16u;
            CP_ASYNC16(sa + off, As + (size_t)row * lda + gr * 8);
            CP_ASYNC16(sb + off, Bs + (size_t)row * ldb + gr * 8);
        }
    };

    load_chunk(0, 0); CP_COMMIT();
    load_chunk(1, 1); CP_COMMIT();

    const int lrow = lane & 15;
    const int lcol = (lane >> 4) * 16;

    int stage = 0;
    for (int c = 0; c < nchunk; ++c) {
        CP_WAIT1();
        __syncthreads();
        if (c + 2 < nchunk) load_chunk(c + 2, (stage + 2) % 3);
        CP_COMMIT();

        uint32_t sa = sbase + stage * STAGE_BYTES;
        uint32_t sb = sa + 128 * PITCH;

#pragma unroll
        for (int ks = 0; ks < 4; ks++) {
            uint32_t afrag[2][4];
#pragma unroll
            for (int mt = 0; mt < 2; mt++) {
                uint32_t addr = sa + (uint32_t)(warp_m * 32 + mt * 16 + lrow) * PITCH
                              + ks * 32 + lcol;
                LDSM_X4(afrag[mt][0], afrag[mt][1], afrag[mt][2], afrag[mt][3], addr);
            }
            uint32_t bfrag[8][2];
#pragma unroll
            for (int nq = 0; nq < 4; nq++) {
                uint32_t t0, t1, t2, t3;
                uint32_t addr = sb + (uint32_t)(warp_n * 64 + nq * 16 + lrow) * PITCH
                              + ks * 32 + lcol;
                LDSM_X4(t0, t1, t2, t3, addr);
                bfrag[nq * 2 + 0][0] = t0; bfrag[nq * 2 + 0][1] = t2;
                bfrag[nq * 2 + 1][0] = t1; bfrag[nq * 2 + 1][1] = t3;
            }
#pragma unroll
            for (int mt = 0; mt < 2; mt++)
#pragma unroll
                for (int nt = 0; nt < 8; nt++)
                    MMA16816(acc[mt][nt], afrag[mt], bfrag[nt]);
        }
        stage = (stage == 2) ? 0 : stage + 1;
    }

    // epilogue
    const int crow = lane >> 2;
    const int ccol = (lane & 3) * 2;
#pragma unroll
    for (int mt = 0; mt < 2; mt++) {
#pragma unroll
        for (int nt = 0; nt < 8; nt++) {
            float* p = Cg + (size_t)(warp_m * 32 + mt * 16 + crow) * ldc
                         + warp_n * 64 + nt * 8 + ccol;
            *(float2*)p = make_float2(acc[mt][nt][0], acc[mt][nt][1]);
            *(float2*)(p + 8 * ldc) = make_float2(acc[mt][nt][2], acc[mt][nt][3]);
        }
    }
    if (maxArr) {
        unsigned* mrow = maxArr + b * NK + blockIdx.x * 128 + warp_n * 64;
#pragma unroll
        for (int nt = 0; nt < 8; nt++) {
            float c0 = fmaxf(fmaxf(acc[0][nt][0], acc[0][nt][2]),
                             fmaxf(acc[1][nt][0], acc[1][nt][2]));
            float c1 = fmaxf(fmaxf(acc[0][nt][1], acc[0][nt][3]),
                             fmaxf(acc[1][nt][1], acc[1][nt][3]));
#pragma unroll
            for (int off = 4; off < 32; off <<= 1) {
                c0 = fmaxf(c0, __shfl_xor_sync(0xffffffffu, c0, off));
                c1 = fmaxf(c1, __shfl_xor_sync(0xffffffffu, c1, off));
            }
            if (lane < 4) {
                atomicMax(&mrow[nt * 8 + (lane & 3) * 2],     fmax_flip(c0));
                atomicMax(&mrow[nt * 8 + (lane & 3) * 2 + 1], fmax_flip(c1));
            }
        }
    }
}

// ---------------------------------------------------------------------------
// Single-pass column softmax, column-pair vectorized (float2 / bf16x2).
// Block covers 64 k-columns; thread owns 2 adjacent columns.
// ---------------------------------------------------------------------------
__global__ __launch_bounds__(256) void col_softmax() {
    const int blk = blockIdx.x;
    const int b = blk / (NK / 64);
    const int kbase = (blk % (NK / 64)) * 64;
    const int tid = threadIdx.x;
    const int c2 = (tid & 31) * 2;       // column pair within 64
    const int rg = tid >> 5;             // 0..7

    const float* S = gS + (size_t)b * NQ * NK + kbase;
    __nv_bfloat16* E = gEp + (size_t)b * NQ * 4096 + kbase;
    __shared__ float red[8][64];

    const float m0 = fmax_unflip(gMax[b * NK + kbase + c2]);
    const float m1 = fmax_unflip(gMax[b * NK + kbase + c2 + 1]);

    float s0 = 0.f, s1 = 0.f;
#pragma unroll 4
    for (int q = rg; q < NQ; q += 8) {
        float2 v = *(const float2*)(S + (size_t)q * NK + c2);
        float e0 = __expf(v.x - m0);
        float e1 = __expf(v.y - m1);
        __nv_bfloat16 h0 = __float2bfloat16_rn(e0);
        __nv_bfloat16 h1 = __float2bfloat16_rn(e1);
        __nv_bfloat16 l0 = __float2bfloat16_rn(e0 - __bfloat162float(h0));
        __nv_bfloat16 l1 = __float2bfloat16_rn(e1 - __bfloat162float(h1));
        __nv_bfloat16* r = E + (size_t)q * 4096;
        *(__nv_bfloat162*)(r + c2)        = __nv_bfloat162(h0, h1);
        *(__nv_bfloat162*)(r + 2048 + c2) = __nv_bfloat162(l0, l1);
        s0 += e0;
        s1 += e1;
    }
    red[rg][c2] = s0;
    red[rg][c2 + 1] = s1;
    __syncthreads();
    if (rg < 2) {
        int cc = c2 + rg;                // covers 64 columns with 64 threads
        float s = 0.f;
#pragma unroll
        for (int r = 0; r < 8; r++) s += red[r][cc];
        gRecip[b * NK + kbase + cc] = 1.0f / s;
    }
}

// ---------------------------------------------------------------------------
extern "C" void kernel_launch(void* const* d_in, const int* in_sizes, int n_in,
                              void* d_out, int out_size) {
    const float* Qm = (const float*)d_in[0];
    const float* Km = (const float*)d_in[1];
    const float* Vm = (const float*)d_in[2];
    float* Out = (float*)d_out;

    void *pQ, *pK, *pV, *pE, *pS, *pMax;
    cudaGetSymbolAddress(&pQ, gQp);
    cudaGetSymbolAddress(&pK, gKp);
    cudaGetSymbolAddress(&pV, gVT);
    cudaGetSymbolAddress(&pE, gEp);
    cudaGetSymbolAddress(&pS, gS);
    cudaGetSymbolAddress(&pMax, gMax);

    const int SMEM = 3 * STAGE_BYTES;   // 110592
    static bool attr_done = false;
    if (!attr_done) {
        cudaFuncSetAttribute(tc_gemm, cudaFuncAttributeMaxDynamicSharedMemorySize, SMEM);
        attr_done = true;
    }

    split_qk<<<dim3(NB * NQ, 2), 256>>>(Qm, Km);

    // S = Q' @ K'^T with fused column-max
    tc_gemm<<<dim3(NK / 128, NQ / 128, NB), 256, SMEM>>>(
        (const __nv_bfloat16*)pQ, (const __nv_bfloat16*)pK, (float*)pS,
        2048, 2048, NK, 16,
        (size_t)NQ * 2048, (size_t)NK * 2048, (size_t)NQ * NK,
        (unsigned*)pMax);

    col_softmax<<<NB * (NK / 64), 256>>>();

    transpose_v<<<dim3(ND / 32, NK / 32, NB), 256>>>(Vm);

    // Out = E' @ VT'^T
    tc_gemm<<<dim3(ND / 128, NQ / 128, NB), 256, SMEM>>>(
        (const __nv_bfloat16*)pE, (const __nv_bfloat16*)pV, Out,
        4096, 4096, ND, 32,
        (size_t)NQ * 4096, (size_t)ND * 4096, (size_t)NQ * ND,
        (unsigned*)nullptr);
}